// round 8
// baseline (speedup 1.0000x reference)
#include <cuda_runtime.h>

typedef unsigned long long u64;

#define NP 64
#define NCOLS 500000
#define BCOLS 256
#define NB    ((NCOLS + BCOLS - 1) / BCOLS)   /* 1954 */
#define NANG 2016
#define NSEG  8
#define SEGL  (NANG / NSEG)                   /* 252 rotations per segment */
#define KCH   16                              /* K rows per staged chunk */
#define NCH   (NP / KCH)                      /* 4 chunks */

// RT[k*64 + i] = mus[i] * R[i][k]
__device__ float d_RT[NP * NP];
// segment products, column-major: d_SEG[b*4096 + j*64 + i] = S_b[i][j]
__device__ __align__(16) float d_SEG[NSEG * NP * NP];

// ---------------------------------------------------------------------------
// Kernel 1a: segment products. Block b applies rotations [b*252,(b+1)*252)
// to the identity. Thread j owns column j (stride-64 smem, conflict-free).
// 8 blocks run in parallel -> serial chain cut from 2016 to 252 rotations.
// ---------------------------------------------------------------------------
__global__ void __launch_bounds__(64)
seg_kernel(const float* __restrict__ angles) {
    __shared__ float2 cs[SEGL];
    __shared__ float  M[(NP + 1) * NP];       // row 64 = pad for prefetch
    const int b = blockIdx.x;
    const int j = threadIdx.x;
    const int k0 = b * SEGL;

    for (int t = j; t < SEGL; t += NP) {
        float s, c;
        sincosf(angles[k0 + t], &s, &c);
        cs[t] = make_float2(c, s);
    }
    #pragma unroll
    for (int i = 0; i < NP + 1; i++) M[i * NP + j] = (i == j) ? 1.0f : 0.0f;
    __syncthreads();

    // walker: global rotation index k0 -> (it, ib)
    int it = 0, rem = k0;
    while (rem >= 63 - it) { rem -= 63 - it; it++; }
    int ib = it + 1 + rem;

    float* col = &M[j];
    float vt = col[it * NP];
    float mb = col[ib * NP];

    for (int t = 0; t < SEGL; t++) {
        int itn = it, ibn = ib + 1;
        if (ibn == NP) { itn = it + 1; ibn = itn + 1; }

        const float2 c_s = cs[t];
        const float  mbn = col[ibn * NP];     // prefetch (row 64 pad-safe)
        const float  smb = c_s.y * mb;
        const float  cmb = c_s.x * mb;
        const float  nb  = fmaf(c_s.y, vt, cmb);    // vb' = s*vt + c*vb
        const float  nvt = fmaf(c_s.x, vt, -smb);   // vt' = c*vt - s*vb
        col[ib * NP] = nb;

        if (itn != it) {                      // sweep boundary (uniform branch)
            col[it * NP] = nvt;
            vt = col[itn * NP];
            mb = col[ibn * NP];
        } else {
            vt = nvt;
            mb = mbn;
        }
        it = itn; ib = ibn;
    }
    col[it * NP] = vt;                        // flush in-progress top row
    __syncthreads();

    // write column-major: d_SEG[b][j*64 + i] = M[i][j]
    float* Sg = d_SEG + b * (NP * NP) + j * NP;
    for (int i = 0; i < NP; i++) Sg[i] = M[i * NP + j];
}

// ---------------------------------------------------------------------------
// Kernel 1b: combine. One block: P = S0; for s=1..7: P = S_s * P.
// Thread (q=tid>>6, j=tid&63) computes rows q*16..+16 of column j.
// A (=S_s) read from global (uniform per-warp float4 loads, L1-cached);
// B column j = P column (smem, thread-local).  Finally RT = (diag(mus)*P)^T.
// ---------------------------------------------------------------------------
__global__ void __launch_bounds__(256)
combine_kernel(const float* __restrict__ mus) {
    __shared__ float P[2][NP * NP];           // column-major, ping-pong
    const int tid = threadIdx.x;
    const int j = tid & 63;
    const int q = tid >> 6;

    for (int t = tid; t < NP * NP; t += 256) P[0][t] = d_SEG[t];
    __syncthreads();

    int cur = 0;
    for (int s = 1; s < NSEG; s++) {
        const float* Sg = d_SEG + s * (NP * NP);
        const float* Pc = &P[cur][j * NP];
        float acc[16];
        #pragma unroll
        for (int i = 0; i < 16; i++) acc[i] = 0.0f;

        for (int k = 0; k < NP; k++) {
            const float bv = Pc[k];
            const float4* A4 = (const float4*)(Sg + k * NP + q * 16);
            const float4 a0 = A4[0], a1 = A4[1], a2 = A4[2], a3 = A4[3];
            acc[ 0] = fmaf(a0.x, bv, acc[ 0]);
            acc[ 1] = fmaf(a0.y, bv, acc[ 1]);
            acc[ 2] = fmaf(a0.z, bv, acc[ 2]);
            acc[ 3] = fmaf(a0.w, bv, acc[ 3]);
            acc[ 4] = fmaf(a1.x, bv, acc[ 4]);
            acc[ 5] = fmaf(a1.y, bv, acc[ 5]);
            acc[ 6] = fmaf(a1.z, bv, acc[ 6]);
            acc[ 7] = fmaf(a1.w, bv, acc[ 7]);
            acc[ 8] = fmaf(a2.x, bv, acc[ 8]);
            acc[ 9] = fmaf(a2.y, bv, acc[ 9]);
            acc[10] = fmaf(a2.z, bv, acc[10]);
            acc[11] = fmaf(a2.w, bv, acc[11]);
            acc[12] = fmaf(a3.x, bv, acc[12]);
            acc[13] = fmaf(a3.y, bv, acc[13]);
            acc[14] = fmaf(a3.z, bv, acc[14]);
            acc[15] = fmaf(a3.w, bv, acc[15]);
        }
        float* Pd = &P[cur ^ 1][j * NP + q * 16];
        #pragma unroll
        for (int i = 0; i < 16; i++) Pd[i] = acc[i];
        __syncthreads();
        cur ^= 1;
    }
    // d_RT[k*64+i] = P[i][k]*mus[i]; column-major P: P[i][k] = Psm[k*64+i]
    for (int t = tid; t < NP * NP; t += 256)
        d_RT[t] = P[cur][t] * mus[t & 63];
}

// ---------------------------------------------------------------------------
// cp.async helpers
// ---------------------------------------------------------------------------
__device__ __forceinline__ void cpa16(void* smem, const void* g) {
    unsigned s = (unsigned)__cvta_generic_to_shared(smem);
    asm volatile("cp.async.cg.shared.global [%0], [%1], 16;\n" :: "r"(s), "l"(g));
}
__device__ __forceinline__ void cpa_commit() {
    asm volatile("cp.async.commit_group;\n");
}
template <int N>
__device__ __forceinline__ void cpa_wait() {
    asm volatile("cp.async.wait_group %0;\n" :: "n"(N));
}
__device__ __forceinline__ void fma2(u64& d, u64 a, u64 b) {
    asm("fma.rn.f32x2 %0, %1, %2, %0;" : "+l"(d) : "l"(a), "l"(b));
}
__device__ __forceinline__ u64 dup2(float v) {
    u64 r;
    asm("mov.b64 %0, {%1, %1};" : "=l"(r) : "r"(__float_as_uint(v)));
    return r;
}

// ---------------------------------------------------------------------------
// Kernel 2: Y = M @ X (verbatim the 100.35us variant).
// Block: 64 rows x 256 cols, 8 warps, 2 blocks/SM. X staged via cp.async in
// 16-row chunks (double-buffered). Thread: 8 rows x 8 cols.
// ---------------------------------------------------------------------------
__global__ void __launch_bounds__(256, 2)
gemm_kernel(const float* __restrict__ X, float* __restrict__ out) {
    __shared__ __align__(16) u64   sR[NP * NP];          // dup (v,v), 32 KB
    __shared__ __align__(16) float sX[2][KCH * BCOLS];   // 2 x 16 KB

    const int tid = threadIdx.x;
    const float4* R4 = (const float4*)d_RT;
    for (int t = tid; t < NP * NP / 4; t += 256) {
        float4 v = R4[t];
        sR[t * 4 + 0] = dup2(v.x);
        sR[t * 4 + 1] = dup2(v.y);
        sR[t * 4 + 2] = dup2(v.z);
        sR[t * 4 + 3] = dup2(v.w);
    }

    const int lane = tid & 31;
    const int wid  = tid >> 5;
    const int col0 = blockIdx.x * BCOLS;

    const int lrow = tid >> 4;                 // 0..15
    const int gcol = col0 + (tid & 15) * 16;
    const int c0 = min(gcol +  0, NCOLS - 4);
    const int c1 = min(gcol +  4, NCOLS - 4);
    const int c2 = min(gcol +  8, NCOLS - 4);
    const int c3 = min(gcol + 12, NCOLS - 4);
    float* sdst0 = &sX[0][lrow * BCOLS + (tid & 15) * 16];
    float* sdst1 = &sX[1][lrow * BCOLS + (tid & 15) * 16];

    {   // prefetch chunks 0 and 1
        size_t ro = (size_t)lrow * NCOLS;
        cpa16(sdst0 +  0, X + ro + c0);  cpa16(sdst0 +  4, X + ro + c1);
        cpa16(sdst0 +  8, X + ro + c2);  cpa16(sdst0 + 12, X + ro + c3);
        cpa_commit();
        ro += (size_t)KCH * NCOLS;
        cpa16(sdst1 +  0, X + ro + c0);  cpa16(sdst1 +  4, X + ro + c1);
        cpa16(sdst1 +  8, X + ro + c2);  cpa16(sdst1 + 12, X + ro + c3);
        cpa_commit();
    }

    u64 aA[8][2], aB[8][2];
    #pragma unroll
    for (int il = 0; il < 8; il++) {
        aA[il][0] = aA[il][1] = 0ULL;
        aB[il][0] = aB[il][1] = 0ULL;
    }

    const int rbase = wid * 4;

    #pragma unroll 1
    for (int ch = 0; ch < NCH; ch++) {
        if (ch == NCH - 1) cpa_wait<0>(); else cpa_wait<1>();
        __syncthreads();

        const ulonglong2* xc  = (const ulonglong2*)&sX[ch & 1][0];
        const ulonglong2* sR2 = (const ulonglong2*)sR;
        #pragma unroll
        for (int k = 0; k < KCH; k++) {
            const ulonglong2 cA = xc[k * (BCOLS / 4) + lane];
            const ulonglong2 cB = xc[k * (BCOLS / 4) + lane + 32];
            ulonglong2 rv[4];
            #pragma unroll
            for (int u = 0; u < 4; u++)
                rv[u] = sR2[(ch * KCH + k) * 32 + rbase + u];
            #pragma unroll
            for (int il = 0; il < 8; il++) {
                const u64 Rd = (il & 1) ? rv[il >> 1].y : rv[il >> 1].x;
                fma2(aA[il][0], Rd, cA.x);
                fma2(aA[il][1], Rd, cA.y);
                fma2(aB[il][0], Rd, cB.x);
                fma2(aB[il][1], Rd, cB.y);
            }
        }
        __syncthreads();

        if (ch + 2 < NCH) {
            size_t ro = (size_t)(lrow + (ch + 2) * KCH) * NCOLS;
            float* d = (ch & 1) ? sdst1 : sdst0;
            cpa16(d +  0, X + ro + c0);  cpa16(d +  4, X + ro + c1);
            cpa16(d +  8, X + ro + c2);  cpa16(d + 12, X + ro + c3);
        }
        cpa_commit();
    }

    const int colA = col0 + lane * 4;
    const int colB = colA + 128;
    #pragma unroll
    for (int il = 0; il < 8; il++) {
        const int i = wid * 8 + il;
        if (colA < NCOLS) {
            ulonglong2 v; v.x = aA[il][0]; v.y = aA[il][1];
            *(ulonglong2*)(out + (size_t)i * NCOLS + colA) = v;
        }
        if (colB < NCOLS) {
            ulonglong2 v; v.x = aB[il][0]; v.y = aB[il][1];
            *(ulonglong2*)(out + (size_t)i * NCOLS + colB) = v;
        }
    }
}

// ---------------------------------------------------------------------------
extern "C" void kernel_launch(void* const* d_in, const int* in_sizes, int n_in,
                              void* d_out, int out_size) {
    const float* X      = (const float*)d_in[0];
    const float* angles = (const float*)d_in[1];
    const float* mus    = (const float*)d_in[2];
    float*       out    = (float*)d_out;

    seg_kernel<<<NSEG, NP>>>(angles);
    combine_kernel<<<1, 256>>>(mus);
    gemm_kernel<<<NB, 256>>>(X, out);
}

// round 9
// speedup vs baseline: 1.4174x; 1.4174x over previous
#include <cuda_runtime.h>

typedef unsigned long long u64;

#define NP 64
#define NCOLS 500000
#define BCOLS 256
#define NB    ((NCOLS + BCOLS - 1) / BCOLS)   /* 1954 gemm blocks */
#define NANG 2016
#define NSEG  8
#define SEGL  (NANG / NSEG)                   /* 252 rotations per segment */
#define KCH   16                              /* K rows per staged chunk */
#define NCH   (NP / KCH)                      /* 4 chunks */

// RT[k*64 + i] = mus[i] * R[i][k]
__device__ float d_RT[NP * NP];
// segment products, column-major: d_SEG[b*4096 + j*64 + i] = S_b[i][j]
__device__ __align__(16) float d_SEG[NSEG * NP * NP];
__device__ int d_segdone = 0;   // segments completed   (reset by block 0)
__device__ int d_flag    = 0;   // R ready              (reset by last gemm block)
__device__ int d_done    = 0;   // gemm blocks past spin (self-resetting)

// ---------------------------------------------------------------------------
// helpers
// ---------------------------------------------------------------------------
__device__ __forceinline__ void cpa16(void* smem, const void* g) {
    unsigned s = (unsigned)__cvta_generic_to_shared(smem);
    asm volatile("cp.async.cg.shared.global [%0], [%1], 16;\n" :: "r"(s), "l"(g));
}
__device__ __forceinline__ void cpa_commit() {
    asm volatile("cp.async.commit_group;\n");
}
template <int N>
__device__ __forceinline__ void cpa_wait() {
    asm volatile("cp.async.wait_group %0;\n" :: "n"(N));
}
__device__ __forceinline__ void fma2(u64& d, u64 a, u64 b) {
    asm("fma.rn.f32x2 %0, %1, %2, %0;" : "+l"(d) : "l"(a), "l"(b));
}
__device__ __forceinline__ u64 dup2(float v) {
    u64 r;
    asm("mov.b64 %0, {%1, %1};" : "=l"(r) : "r"(__float_as_uint(v)));
    return r;
}

// ---------------------------------------------------------------------------
// ONE fused kernel.
//   blocks 0..7   : build segment products S_b (252 rotations, parallel)
//   block  0      : afterwards combines S_7*...*S_0, scales by mus -> d_RT
//   blocks 8..    : cp.async X prologue, brief spin on d_flag, then GEMM
// ---------------------------------------------------------------------------
__global__ void __launch_bounds__(256, 2)
fused_kernel(const float* __restrict__ X,
             const float* __restrict__ angles,
             const float* __restrict__ mus,
             float* __restrict__ out) {
    __shared__ __align__(16) u64   sR[NP * NP];          // 32 KB
    __shared__ __align__(16) float sX[2][KCH * BCOLS];   // 32 KB

    const int tid = threadIdx.x;

    // =======================================================================
    // Builder blocks
    // =======================================================================
    if (blockIdx.x < NSEG) {
        const int b = blockIdx.x;
        float2* cs = (float2*)sR;            // 252*8B, aliased
        float*  M  = (float*)sX;             // 65*64*4B, aliased

        for (int t = tid; t < SEGL; t += 256) {
            float s, c;
            sincosf(angles[b * SEGL + t], &s, &c);
            cs[t] = make_float2(c, s);
        }
        if (tid < NP) {
            #pragma unroll
            for (int i = 0; i < NP + 1; i++)
                M[i * NP + tid] = (i == tid) ? 1.0f : 0.0f;
        }
        __syncthreads();

        if (tid < NP) {
            const int j = tid;
            // walker: rotation index b*SEGL -> (it, ib)
            int it = 0, rem = b * SEGL;
            while (rem >= 63 - it) { rem -= 63 - it; it++; }
            int ib = it + 1 + rem;

            float* col = &M[j];
            float vt = col[it * NP];
            float mb = col[ib * NP];
            for (int t = 0; t < SEGL; t++) {
                int itn = it, ibn = ib + 1;
                if (ibn == NP) { itn = it + 1; ibn = itn + 1; }
                const float2 c_s = cs[t];
                const float  mbn = col[ibn * NP];        // row-64 pad-safe
                const float  smb = c_s.y * mb;
                const float  cmb = c_s.x * mb;
                const float  nb  = fmaf(c_s.y, vt, cmb);   // vb' = s*vt + c*vb
                const float  nvt = fmaf(c_s.x, vt, -smb);  // vt' = c*vt - s*vb
                col[ib * NP] = nb;
                if (itn != it) {                         // sweep boundary
                    col[it * NP] = nvt;
                    vt = col[itn * NP];
                    mb = col[ibn * NP];
                } else { vt = nvt; mb = mbn; }
                it = itn; ib = ibn;
            }
            col[it * NP] = vt;
        }
        __syncthreads();
        if (tid < NP) {                      // column-major S_b
            float* Sg = d_SEG + b * (NP * NP) + tid * NP;
            for (int i = 0; i < NP; i++) Sg[i] = M[i * NP + tid];
        }
        __syncthreads();
        if (tid == 0) {
            __threadfence();
            atomicAdd(&d_segdone, 1);
        }
        if (b != 0) return;

        // ---- block 0: combine P = S7 * ... * S0 ----
        if (tid == 0) {
            while (atomicAdd(&d_segdone, 0) < NSEG) __nanosleep(64);
            __threadfence();
        }
        __syncthreads();

        float* P = (float*)sR;               // P[2][4096], 32 KB, aliased
        const int j = tid & 63;
        const int q = tid >> 6;
        for (int t = tid; t < NP * NP; t += 256) P[t] = d_SEG[t];
        __syncthreads();

        int cur = 0;
        for (int s = 1; s < NSEG; s++) {
            const float* Sg = d_SEG + s * (NP * NP);
            const float* Pc = &P[cur * (NP * NP) + j * NP];
            float acc[16];
            #pragma unroll
            for (int i = 0; i < 16; i++) acc[i] = 0.0f;
            for (int k = 0; k < NP; k++) {
                const float bv = Pc[k];
                const float4* A4 = (const float4*)(Sg + k * NP + q * 16);
                const float4 a0 = A4[0], a1 = A4[1], a2 = A4[2], a3 = A4[3];
                acc[ 0] = fmaf(a0.x, bv, acc[ 0]);
                acc[ 1] = fmaf(a0.y, bv, acc[ 1]);
                acc[ 2] = fmaf(a0.z, bv, acc[ 2]);
                acc[ 3] = fmaf(a0.w, bv, acc[ 3]);
                acc[ 4] = fmaf(a1.x, bv, acc[ 4]);
                acc[ 5] = fmaf(a1.y, bv, acc[ 5]);
                acc[ 6] = fmaf(a1.z, bv, acc[ 6]);
                acc[ 7] = fmaf(a1.w, bv, acc[ 7]);
                acc[ 8] = fmaf(a2.x, bv, acc[ 8]);
                acc[ 9] = fmaf(a2.y, bv, acc[ 9]);
                acc[10] = fmaf(a2.z, bv, acc[10]);
                acc[11] = fmaf(a2.w, bv, acc[11]);
                acc[12] = fmaf(a3.x, bv, acc[12]);
                acc[13] = fmaf(a3.y, bv, acc[13]);
                acc[14] = fmaf(a3.z, bv, acc[14]);
                acc[15] = fmaf(a3.w, bv, acc[15]);
            }
            float* Pd = &P[(cur ^ 1) * (NP * NP) + j * NP + q * 16];
            #pragma unroll
            for (int i = 0; i < 16; i++) Pd[i] = acc[i];
            __syncthreads();
            cur ^= 1;
        }
        // d_RT[k*64+i] = P[i][k]*mus[i]  (column-major P: slot k*64+i)
        for (int t = tid; t < NP * NP; t += 256)
            d_RT[t] = P[cur * (NP * NP) + t] * mus[t & 63];
        __syncthreads();
        if (tid == 0) {
            __threadfence();                 // release RT
            d_segdone = 0;                   // restore launch invariants
            atomicExch(&d_flag, 1);
        }
        return;
    }

    // =======================================================================
    // GEMM blocks (proven 100.35us loop)
    // =======================================================================
    const int lane = tid & 31;
    const int wid  = tid >> 5;
    const int col0 = (blockIdx.x - NSEG) * BCOLS;

    const int lrow = tid >> 4;                 // 0..15
    const int gcol = col0 + (tid & 15) * 16;
    const int c0 = min(gcol +  0, NCOLS - 4);
    const int c1 = min(gcol +  4, NCOLS - 4);
    const int c2 = min(gcol +  8, NCOLS - 4);
    const int c3 = min(gcol + 12, NCOLS - 4);
    float* sdst0 = &sX[0][lrow * BCOLS + (tid & 15) * 16];
    float* sdst1 = &sX[1][lrow * BCOLS + (tid & 15) * 16];

    {   // prefetch chunks 0 and 1 (independent of R)
        size_t ro = (size_t)lrow * NCOLS;
        cpa16(sdst0 +  0, X + ro + c0);  cpa16(sdst0 +  4, X + ro + c1);
        cpa16(sdst0 +  8, X + ro + c2);  cpa16(sdst0 + 12, X + ro + c3);
        cpa_commit();
        ro += (size_t)KCH * NCOLS;
        cpa16(sdst1 +  0, X + ro + c0);  cpa16(sdst1 +  4, X + ro + c1);
        cpa16(sdst1 +  8, X + ro + c2);  cpa16(sdst1 + 12, X + ro + c3);
        cpa_commit();
    }

    // wait for R (overlaps the DRAM prologue above)
    if (tid == 0) {
        while (atomicAdd(&d_flag, 0) == 0) __nanosleep(128);
        __threadfence();
        if (atomicAdd(&d_done, 1) == NB - 1) {   // last gemm block past spin
            d_done = 0;
            d_flag = 0;
        }
    }
    __syncthreads();

    // stage R as duplicated (v,v) u64 pairs
    const float4* R4 = (const float4*)d_RT;
    for (int t = tid; t < NP * NP / 4; t += 256) {
        float4 v = R4[t];
        sR[t * 4 + 0] = dup2(v.x);
        sR[t * 4 + 1] = dup2(v.y);
        sR[t * 4 + 2] = dup2(v.z);
        sR[t * 4 + 3] = dup2(v.w);
    }

    u64 aA[8][2], aB[8][2];
    #pragma unroll
    for (int il = 0; il < 8; il++) {
        aA[il][0] = aA[il][1] = 0ULL;
        aB[il][0] = aB[il][1] = 0ULL;
    }

    const int rbase = wid * 4;

    #pragma unroll 1
    for (int ch = 0; ch < NCH; ch++) {
        if (ch == NCH - 1) cpa_wait<0>(); else cpa_wait<1>();
        __syncthreads();

        const ulonglong2* xc  = (const ulonglong2*)&sX[ch & 1][0];
        const ulonglong2* sR2 = (const ulonglong2*)sR;
        #pragma unroll
        for (int k = 0; k < KCH; k++) {
            const ulonglong2 cA = xc[k * (BCOLS / 4) + lane];
            const ulonglong2 cB = xc[k * (BCOLS / 4) + lane + 32];
            ulonglong2 rv[4];
            #pragma unroll
            for (int u = 0; u < 4; u++)
                rv[u] = sR2[(ch * KCH + k) * 32 + rbase + u];
            #pragma unroll
            for (int il = 0; il < 8; il++) {
                const u64 Rd = (il & 1) ? rv[il >> 1].y : rv[il >> 1].x;
                fma2(aA[il][0], Rd, cA.x);
                fma2(aA[il][1], Rd, cA.y);
                fma2(aB[il][0], Rd, cB.x);
                fma2(aB[il][1], Rd, cB.y);
            }
        }
        __syncthreads();

        if (ch + 2 < NCH) {
            size_t ro = (size_t)(lrow + (ch + 2) * KCH) * NCOLS;
            float* d = (ch & 1) ? sdst1 : sdst0;
            cpa16(d +  0, X + ro + c0);  cpa16(d +  4, X + ro + c1);
            cpa16(d +  8, X + ro + c2);  cpa16(d + 12, X + ro + c3);
        }
        cpa_commit();
    }

    const int colA = col0 + lane * 4;
    const int colB = colA + 128;
    #pragma unroll
    for (int il = 0; il < 8; il++) {
        const int i = wid * 8 + il;
        if (colA < NCOLS) {
            ulonglong2 v; v.x = aA[il][0]; v.y = aA[il][1];
            *(ulonglong2*)(out + (size_t)i * NCOLS + colA) = v;
        }
        if (colB < NCOLS) {
            ulonglong2 v; v.x = aB[il][0]; v.y = aB[il][1];
            *(ulonglong2*)(out + (size_t)i * NCOLS + colB) = v;
        }
    }
}

// ---------------------------------------------------------------------------
extern "C" void kernel_launch(void* const* d_in, const int* in_sizes, int n_in,
                              void* d_out, int out_size) {
    const float* X      = (const float*)d_in[0];
    const float* angles = (const float*)d_in[1];
    const float* mus    = (const float*)d_in[2];
    float*       out    = (float*)d_out;

    fused_kernel<<<NB + NSEG, 256>>>(X, angles, mus, out);
}